// round 3
// baseline (speedup 1.0000x reference)
#include <cuda_runtime.h>

// Problem shape (fixed by setup_inputs): f (32,512,512) f32, K (5,5,512,512) f32, dt (32,)
#define BATCH 32
#define H 512
#define W 512
#define KS 5
#define HALO 2

// Tiling: block = 128 threads = 32 (x) * 4 (y-groups); each thread computes a
// vertical pair of pixels (VY=2) -> output tile 32 x 8 per block.
#define TILE_X 32
#define TILE_Y 8
#define VY 2
#define SM_ROWS (TILE_Y + 2 * HALO)   // 12
#define SM_COLS (TILE_X + 2 * HALO)   // 36
#define BCHUNK 16                     // batches staged in smem at a time

__global__ __launch_bounds__(128) void op2d_kernel(
    const float* __restrict__ f,
    const float* __restrict__ Kk,
    const float* __restrict__ dt,
    float* __restrict__ out)
{
    __shared__ float fs[BCHUNK][SM_ROWS][SM_COLS];  // 27648 B
    __shared__ float dts[BATCH];

    const int tid = threadIdx.x;
    const int tx = tid & 31;        // 0..31 (x within tile; one warp per row-group)
    const int ty = tid >> 5;        // 0..3
    const int tileX = blockIdx.x * TILE_X;
    const int tileY = blockIdx.y * TILE_Y;

    if (tid < BATCH) dts[tid] = dt[tid];

    // Per-thread output coordinates (grid divides H,W exactly: 512 = 64*8 = 16*32)
    const int y0 = tileY + ty * VY;
    const int x  = tileX + tx;
    const int ry = ty * VY;         // smem row base: kernel row i of pixel y0 -> fs row ry+i

    // Load the 2*25 per-pixel kernel taps into registers (coalesced along x),
    // reused across all 32 batches.
    float k0[25], k1[25];
    #pragma unroll
    for (int t = 0; t < 25; t++) {
        k0[t] = Kk[(t * H + y0)     * W + x];
        k1[t] = Kk[(t * H + y0 + 1) * W + x];
    }

    for (int bc = 0; bc < BATCH; bc += BCHUNK) {
        __syncthreads();  // previous chunk's compute done before overwrite

        // Cooperative load of BCHUNK batch tiles (with zero halo) into smem.
        const int total = BCHUNK * SM_ROWS * SM_COLS;  // 6912
        for (int idx = tid; idx < total; idx += 128) {
            int c = idx % SM_COLS;
            int t = idx / SM_COLS;
            int r = t % SM_ROWS;
            int b = t / SM_ROWS;
            int gy = tileY + r - HALO;
            int gx = tileX + c - HALO;
            float v = 0.0f;
            if ((unsigned)gy < (unsigned)H && (unsigned)gx < (unsigned)W)
                v = f[((bc + b) * H + gy) * W + gx];
            fs[b][r][c] = v;
        }
        __syncthreads();

        for (int bb = 0; bb < BCHUNK; bb++) {
            float acc0 = 0.0f, acc1 = 0.0f;
            // 6 smem rows cover both stacked pixels' 5-row footprints:
            // row r feeds acc0 (kernel row r, r<5) and acc1 (kernel row r-1, r>=1).
            #pragma unroll
            for (int r = 0; r < 6; r++) {
                float fv0 = fs[bb][ry + r][tx + 0];
                float fv1 = fs[bb][ry + r][tx + 1];
                float fv2 = fs[bb][ry + r][tx + 2];
                float fv3 = fs[bb][ry + r][tx + 3];
                float fv4 = fs[bb][ry + r][tx + 4];
                if (r < 5) {
                    acc0 = fmaf(fv0, k0[r * 5 + 0], acc0);
                    acc0 = fmaf(fv1, k0[r * 5 + 1], acc0);
                    acc0 = fmaf(fv2, k0[r * 5 + 2], acc0);
                    acc0 = fmaf(fv3, k0[r * 5 + 3], acc0);
                    acc0 = fmaf(fv4, k0[r * 5 + 4], acc0);
                }
                if (r >= 1) {
                    acc1 = fmaf(fv0, k1[(r - 1) * 5 + 0], acc1);
                    acc1 = fmaf(fv1, k1[(r - 1) * 5 + 1], acc1);
                    acc1 = fmaf(fv2, k1[(r - 1) * 5 + 2], acc1);
                    acc1 = fmaf(fv3, k1[(r - 1) * 5 + 3], acc1);
                    acc1 = fmaf(fv4, k1[(r - 1) * 5 + 4], acc1);
                }
            }
            const int b = bc + bb;
            float d  = dts[b];
            float f0 = fs[bb][ry + HALO][tx + HALO];      // f[b, y0,   x]
            float f1 = fs[bb][ry + HALO + 1][tx + HALO];  // f[b, y0+1, x]
            float o0 = fmaf(acc0, d, f0);
            float o1 = fmaf(acc1, d, f1);
            out[(b * H + y0)     * W + x] = fmaxf(o0, 0.0f);
            out[(b * H + y0 + 1) * W + x] = fmaxf(o1, 0.0f);
        }
    }
}

extern "C" void kernel_launch(void* const* d_in, const int* in_sizes, int n_in,
                              void* d_out, int out_size)
{
    const float* f  = (const float*)d_in[0];
    const float* Kk = (const float*)d_in[1];
    const float* dt = (const float*)d_in[2];
    float* out = (float*)d_out;

    dim3 grid(W / TILE_X, H / TILE_Y);  // (16, 64) = 1024 blocks
    dim3 block(128);
    op2d_kernel<<<grid, block>>>(f, Kk, dt, out);
}

// round 4
// speedup vs baseline: 1.8112x; 1.8112x over previous
#include <cuda_runtime.h>

// f (32,512,512) f32, K (5,5,512,512) f32, dt (32,) -> out = relu(f + dt * conv_unshared5x5(f, K))
#define BATCH 32
#define H 512
#define W 512
#define HALO 2

// Output tile 32 x 8 per block, 128 threads (32 x, 4 y-groups), VY=2 pixels/thread.
// Batch handled as float4 vectors (4 batches per LDS.128), GSTAGE=4 groups (16
// batches) staged in smem per sync.
#define TILE_X 32
#define TILE_Y 8
#define SM_ROWS 12              // TILE_Y + 2*HALO
#define SM_COLS 36              // TILE_X + 2*HALO
#define NPOS (SM_ROWS * SM_COLS)  // 432
#define GSTAGE 4                // 4 groups of 4 batches = 16 batches per stage

#define FMA4(acc, fv, kk)                     \
    acc.x = fmaf(fv.x, kk, acc.x);            \
    acc.y = fmaf(fv.y, kk, acc.y);            \
    acc.z = fmaf(fv.z, kk, acc.z);            \
    acc.w = fmaf(fv.w, kk, acc.w);

__global__ __launch_bounds__(128) void op2d_kernel(
    const float* __restrict__ f,
    const float* __restrict__ Kk,
    const float* __restrict__ dt,
    float* __restrict__ out)
{
    // Batch-innermost layout: fs[group][row][col] is a float4 holding 4 batches
    // at one spatial position. 4*12*36*16 = 27648 B.
    __shared__ float4 fs[GSTAGE][SM_ROWS][SM_COLS];
    __shared__ __align__(16) float dts[BATCH];

    const int tid = threadIdx.x;
    const int tx = tid & 31;     // 0..31
    const int ty = tid >> 5;     // 0..3
    const int tileX = blockIdx.x * TILE_X;
    const int tileY = blockIdx.y * TILE_Y;

    if (tid < BATCH) dts[tid] = dt[tid];

    const int y0 = tileY + ty * 2;   // thread's top pixel row
    const int x  = tileX + tx;
    const int ry = ty * 2;           // smem row base (kernel row i of y0 -> fs row ry+i)

    // 2 x 25 per-pixel kernel taps in registers, reused across all 32 batches.
    float k0[25], k1[25];
    #pragma unroll
    for (int t = 0; t < 25; t++) {
        k0[t] = Kk[(t * H + y0)     * W + x];
        k1[t] = Kk[(t * H + y0 + 1) * W + x];
    }

    float* outp = out + (size_t)y0 * W + x;

    for (int s = 0; s < 2; s++) {       // 2 stages x 16 batches
        __syncthreads();                 // previous stage's compute done

        // ---- Stage 16 batches: coalesced LDG per batch, conflict-free STS.128 ----
        const int b0 = s * 16;
        for (int p = tid; p < NPOS; p += 128) {
            const int r = p / SM_COLS;
            const int c = p - r * SM_COLS;
            const int gy = tileY + r - HALO;
            const int gx = tileX + c - HALO;
            const bool in = ((unsigned)gy < (unsigned)H) & ((unsigned)gx < (unsigned)W);
            const float* fp = f + (size_t)gy * W + gx;
            #pragma unroll
            for (int g = 0; g < GSTAGE; g++) {
                const int bb = b0 + g * 4;
                float4 v;
                v.x = in ? fp[(size_t)(bb + 0) * (H * W)] : 0.0f;
                v.y = in ? fp[(size_t)(bb + 1) * (H * W)] : 0.0f;
                v.z = in ? fp[(size_t)(bb + 2) * (H * W)] : 0.0f;
                v.w = in ? fp[(size_t)(bb + 3) * (H * W)] : 0.0f;
                fs[g][r][c] = v;
            }
        }
        __syncthreads();

        // ---- Compute: per group, 30 LDS.128 feed 200 FMAs ----
        #pragma unroll
        for (int g = 0; g < GSTAGE; g++) {
            float4 a0 = make_float4(0.f, 0.f, 0.f, 0.f);
            float4 a1 = make_float4(0.f, 0.f, 0.f, 0.f);
            // 6 smem rows cover both stacked pixels' 5-row footprints.
            #pragma unroll
            for (int r = 0; r < 6; r++) {
                float4 fv0 = fs[g][ry + r][tx + 0];
                float4 fv1 = fs[g][ry + r][tx + 1];
                float4 fv2 = fs[g][ry + r][tx + 2];
                float4 fv3 = fs[g][ry + r][tx + 3];
                float4 fv4 = fs[g][ry + r][tx + 4];
                if (r < 5) {
                    FMA4(a0, fv0, k0[r * 5 + 0]);
                    FMA4(a0, fv1, k0[r * 5 + 1]);
                    FMA4(a0, fv2, k0[r * 5 + 2]);
                    FMA4(a0, fv3, k0[r * 5 + 3]);
                    FMA4(a0, fv4, k0[r * 5 + 4]);
                }
                if (r >= 1) {
                    FMA4(a1, fv0, k1[(r - 1) * 5 + 0]);
                    FMA4(a1, fv1, k1[(r - 1) * 5 + 1]);
                    FMA4(a1, fv2, k1[(r - 1) * 5 + 2]);
                    FMA4(a1, fv3, k1[(r - 1) * 5 + 3]);
                    FMA4(a1, fv4, k1[(r - 1) * 5 + 4]);
                }
            }

            const int b = b0 + g * 4;
            const float4 dt4 = *(const float4*)&dts[b];
            const float4 fc0 = fs[g][ry + HALO][tx + HALO];      // f[b.., y0,   x]
            const float4 fc1 = fs[g][ry + HALO + 1][tx + HALO];  // f[b.., y0+1, x]

            float* o = outp + (size_t)b * (H * W);
            o[0]             = fmaxf(fmaf(a0.x, dt4.x, fc0.x), 0.0f);
            o[W]             = fmaxf(fmaf(a1.x, dt4.x, fc1.x), 0.0f);
            o += H * W;
            o[0]             = fmaxf(fmaf(a0.y, dt4.y, fc0.y), 0.0f);
            o[W]             = fmaxf(fmaf(a1.y, dt4.y, fc1.y), 0.0f);
            o += H * W;
            o[0]             = fmaxf(fmaf(a0.z, dt4.z, fc0.z), 0.0f);
            o[W]             = fmaxf(fmaf(a1.z, dt4.z, fc1.z), 0.0f);
            o += H * W;
            o[0]             = fmaxf(fmaf(a0.w, dt4.w, fc0.w), 0.0f);
            o[W]             = fmaxf(fmaf(a1.w, dt4.w, fc1.w), 0.0f);
        }
    }
}

extern "C" void kernel_launch(void* const* d_in, const int* in_sizes, int n_in,
                              void* d_out, int out_size)
{
    const float* f  = (const float*)d_in[0];
    const float* Kk = (const float*)d_in[1];
    const float* dt = (const float*)d_in[2];
    float* out = (float*)d_out;

    dim3 grid(W / TILE_X, H / TILE_Y);  // (16, 64) = 1024 blocks
    dim3 block(128);
    op2d_kernel<<<grid, block>>>(f, Kk, dt, out);
}